// round 2
// baseline (speedup 1.0000x reference)
#include <cuda_runtime.h>

#define BB 16
#define LL 24
#define NN 325
#define DDIM 256
#define HH 8
#define MROWS (BB*LL*NN)   // 124800, divisible by 64

// ---------------- scratch (device globals; no cudaMalloc allowed) ----------
__device__ float g_bufQ[MROWS * DDIM];
__device__ float g_bufK[MROWS * DDIM];
__device__ float g_bufV[MROWS * DDIM];
__device__ float g_bufO[MROWS * DDIM];

__device__ __align__(16) float g_sum[4][DDIM];
__device__ __align__(16) float g_sumsq[4][DDIM];
__device__ __align__(16) float g_scale[4][DDIM];
__device__ __align__(16) float g_shift[4][DDIM];

// ---------------- f32x2 packed math helpers --------------------------------
__device__ __forceinline__ unsigned long long pack2(float x, float y) {
    unsigned long long r;
    asm("mov.b64 %0, {%1, %2};" : "=l"(r) : "f"(x), "f"(y));
    return r;
}
__device__ __forceinline__ unsigned long long fma2(unsigned long long a,
                                                   unsigned long long b,
                                                   unsigned long long c) {
    unsigned long long d;
    asm("fma.rn.f32x2 %0, %1, %2, %3;" : "=l"(d) : "l"(a), "l"(b), "l"(c));
    return d;
}
__device__ __forceinline__ float2 unpack2(unsigned long long v) {
    float2 r;
    asm("mov.b64 {%0, %1}, %2;" : "=f"(r.x), "=f"(r.y) : "l"(v));
    return r;
}

// ---------------- zero the BN stat accumulators (every launch) -------------
__global__ void zero_stats_kernel() {
    int t = threadIdx.x;  // 256 threads
#pragma unroll
    for (int s = 0; s < 4; s++) {
        g_sum[s][t] = 0.f;
        g_sumsq[s][t] = 0.f;
    }
}

// ---------------- GEMM (M x 256) * (256 x 256) + bias, with BN stats -------
// Y[m,o] = sum_k X[m,k] * W[k,o] + b[o]; also accumulate per-channel sum/sumsq.
// Tile: 64(M) x 64(N) x 16(K). 256 threads, each computes 4 rows x 4 cols,
// the 4 cols held as 2 packed f32x2 accumulators (FFMA2 = full-rate fp32).
__global__ __launch_bounds__(256) void gemm_bn_kernel(
    const float* __restrict__ X, const float* __restrict__ W,
    const float* __restrict__ bias, float* __restrict__ Y, int set)
{
    __shared__ float Xs[16][68];   // [k][m], padded
    __shared__ float Ws[16][64];   // [k][n]
    __shared__ float s_sum[64], s_sq[64];

    const int tid = threadIdx.x;
    const int tx = tid & 15;       // col group
    const int ty = tid >> 4;       // row group
    const int bm = blockIdx.x >> 2;        // 0..1949
    const int bn = blockIdx.x & 3;         // 0..3
    const int m0 = bm * 64, n0 = bn * 64;

    if (tid < 64) { s_sum[tid] = 0.f; s_sq[tid] = 0.f; }

    unsigned long long acc[4][2];
#pragma unroll
    for (int i = 0; i < 4; i++) { acc[i][0] = 0ull; acc[i][1] = 0ull; }

    const int xrow = tid >> 2;            // 0..63
    const int xk4  = (tid & 3) << 2;      // 0,4,8,12
    const int wrow = tid >> 4;            // 0..15
    const int wc4  = (tid & 15) << 2;     // 0..60

    const float* Xp = X + (size_t)(m0 + xrow) * DDIM + xk4;
    const float* Wp = W + (size_t)wrow * DDIM + n0 + wc4;

    for (int k0 = 0; k0 < DDIM; k0 += 16) {
        float4 xv = *reinterpret_cast<const float4*>(Xp + k0);
        Xs[xk4 + 0][xrow] = xv.x;
        Xs[xk4 + 1][xrow] = xv.y;
        Xs[xk4 + 2][xrow] = xv.z;
        Xs[xk4 + 3][xrow] = xv.w;
        *reinterpret_cast<float4*>(&Ws[wrow][wc4]) =
            *reinterpret_cast<const float4*>(Wp + (size_t)k0 * DDIM);
        __syncthreads();
#pragma unroll
        for (int k = 0; k < 16; k++) {
            float4 xr = *reinterpret_cast<const float4*>(&Xs[k][ty << 2]);
            unsigned long long w01 =
                *reinterpret_cast<const unsigned long long*>(&Ws[k][tx << 2]);
            unsigned long long w23 =
                *reinterpret_cast<const unsigned long long*>(&Ws[k][(tx << 2) + 2]);
            unsigned long long x0 = pack2(xr.x, xr.x);
            unsigned long long x1 = pack2(xr.y, xr.y);
            unsigned long long x2 = pack2(xr.z, xr.z);
            unsigned long long x3 = pack2(xr.w, xr.w);
            acc[0][0] = fma2(x0, w01, acc[0][0]);
            acc[0][1] = fma2(x0, w23, acc[0][1]);
            acc[1][0] = fma2(x1, w01, acc[1][0]);
            acc[1][1] = fma2(x1, w23, acc[1][1]);
            acc[2][0] = fma2(x2, w01, acc[2][0]);
            acc[2][1] = fma2(x2, w23, acc[2][1]);
            acc[3][0] = fma2(x3, w01, acc[3][0]);
            acc[3][1] = fma2(x3, w23, acc[3][1]);
        }
        __syncthreads();
    }

    // epilogue: bias, store, per-channel stats
    const int col = n0 + (tx << 2);
    float4 bz = *reinterpret_cast<const float4*>(&bias[col]);
    float csum[4] = {0.f, 0.f, 0.f, 0.f};
    float csq[4]  = {0.f, 0.f, 0.f, 0.f};
#pragma unroll
    for (int i = 0; i < 4; i++) {
        float2 a = unpack2(acc[i][0]);
        float2 b = unpack2(acc[i][1]);
        float y0 = a.x + bz.x, y1 = a.y + bz.y, y2 = b.x + bz.z, y3 = b.y + bz.w;
        float4 yv = make_float4(y0, y1, y2, y3);
        *reinterpret_cast<float4*>(
            &Y[(size_t)(m0 + (ty << 2) + i) * DDIM + col]) = yv;
        csum[0] += y0; csq[0] += y0 * y0;
        csum[1] += y1; csq[1] += y1 * y1;
        csum[2] += y2; csq[2] += y2 * y2;
        csum[3] += y3; csq[3] += y3 * y3;
    }
#pragma unroll
    for (int j = 0; j < 4; j++) {
        atomicAdd(&s_sum[(tx << 2) + j], csum[j]);
        atomicAdd(&s_sq[(tx << 2) + j], csq[j]);
    }
    __syncthreads();
    if (tid < 64) {
        atomicAdd(&g_sum[set][n0 + tid], s_sum[tid]);
        atomicAdd(&g_sumsq[set][n0 + tid], s_sq[tid]);
    }
}

// ---------------- finalize BN: per-channel scale/shift ---------------------
__global__ void finalize_bn_kernel(const float* __restrict__ gamma,
                                   const float* __restrict__ beta, int set) {
    int o = threadIdx.x;  // 256
    const float invM = 1.f / (float)MROWS;
    float mu  = g_sum[set][o] * invM;
    float var = g_sumsq[set][o] * invM - mu * mu;
    float sc = gamma[o] * rsqrtf(var + 1e-5f);
    g_scale[set][o] = sc;
    g_shift[set][o] = beta[o] - mu * sc;
}

// ---------------- attention ------------------------------------------------
// One block per (b, n, chunk-half). Each half covers 16 chunks of H=8 -> 128
// features. Loads q/k/v (normalized+ReLU on the fly) into SMEM with
// chunk-major, pad-196 layout (conflict-free f32x4 reads), then each thread
// computes one (chunk, lf) output row: 24-wide softmax over K, 8-dim output.
__global__ __launch_bounds__(256) void attn_kernel(
    const float* __restrict__ Yq, const float* __restrict__ Yk,
    const float* __restrict__ Yv, float* __restrict__ O)
{
    __shared__ float qs[16 * 196];
    __shared__ float ks[16 * 196];
    __shared__ float vs[16 * 196];

    const int blk  = blockIdx.x;       // 0..10399
    const int half = blk & 1;
    const int pair = blk >> 1;         // 0..5199
    const int b = pair / NN;
    const int n = pair % NN;
    const int dbase = half * 128;

    for (int idx = threadIdx.x; idx < LL * 128; idx += 256) {
        int l  = idx >> 7;       // 0..23
        int dd = idx & 127;
        int d  = dbase + dd;
        int c  = dd >> 3, h = dd & 7;
        int so = c * 196 + l * 8 + h;
        size_t g = ((size_t)(b * LL + l) * NN + n) * DDIM + d;
        qs[so] = fmaxf(fmaf(Yq[g], g_scale[0][d], g_shift[0][d]), 0.f);
        ks[so] = fmaxf(fmaf(Yk[g], g_scale[1][d], g_shift[1][d]), 0.f);
        vs[so] = fmaxf(fmaf(Yv[g], g_scale[2][d], g_shift[2][d]), 0.f);
    }
    __syncthreads();

    const float inv_scale = 0.17677669529663687f;  // 1/sqrt(32)

    for (int task = threadIdx.x; task < 16 * LL; task += 256) {
        int c  = task & 15;
        int lf = task >> 4;
        const float* qr = &qs[c * 196 + lf * 8];
        float4 q0 = *reinterpret_cast<const float4*>(qr);
        float4 q1 = *reinterpret_cast<const float4*>(qr + 4);

        float sc[24];
        float mx = -1e30f;
#pragma unroll
        for (int p = 0; p < 24; p++) {
            const float* kr = &ks[c * 196 + p * 8];
            float4 k0 = *reinterpret_cast<const float4*>(kr);
            float4 k1 = *reinterpret_cast<const float4*>(kr + 4);
            float s = q0.x * k0.x + q0.y * k0.y + q0.z * k0.z + q0.w * k0.w +
                      q1.x * k1.x + q1.y * k1.y + q1.z * k1.z + q1.w * k1.w;
            s *= inv_scale;
            sc[p] = s;
            mx = fmaxf(mx, s);
        }
        float ssum = 0.f;
#pragma unroll
        for (int p = 0; p < 24; p++) {
            float e = __expf(sc[p] - mx);
            sc[p] = e;
            ssum += e;
        }
        float inv = 1.f / ssum;
        float o[8] = {0.f, 0.f, 0.f, 0.f, 0.f, 0.f, 0.f, 0.f};
#pragma unroll
        for (int p = 0; p < 24; p++) {
            float a = sc[p] * inv;
            const float* vr = &vs[c * 196 + p * 8];
            float4 v0 = *reinterpret_cast<const float4*>(vr);
            float4 v1 = *reinterpret_cast<const float4*>(vr + 4);
            o[0] = fmaf(a, v0.x, o[0]);
            o[1] = fmaf(a, v0.y, o[1]);
            o[2] = fmaf(a, v0.z, o[2]);
            o[3] = fmaf(a, v0.w, o[3]);
            o[4] = fmaf(a, v1.x, o[4]);
            o[5] = fmaf(a, v1.y, o[5]);
            o[6] = fmaf(a, v1.z, o[6]);
            o[7] = fmaf(a, v1.w, o[7]);
        }
        size_t g = ((size_t)(b * LL + lf) * NN + n) * DDIM + dbase + c * 8;
        *reinterpret_cast<float4*>(&O[g]) = make_float4(o[0], o[1], o[2], o[3]);
        *reinterpret_cast<float4*>(&O[g + 4]) = make_float4(o[4], o[5], o[6], o[7]);
    }
}

// ---------------- final normalize + relu -> d_out --------------------------
__global__ __launch_bounds__(256) void norm_out_kernel(
    const float* __restrict__ Z, float* __restrict__ out)
{
    size_t i = (size_t)blockIdx.x * 256 + threadIdx.x;  // one float4 each
    size_t idx = i * 4;
    int d = (int)(idx & 255);
    float4 z = *reinterpret_cast<const float4*>(&Z[idx]);
    float4 s = *reinterpret_cast<const float4*>(&g_scale[3][d]);
    float4 t = *reinterpret_cast<const float4*>(&g_shift[3][d]);
    float4 r;
    r.x = fmaxf(fmaf(z.x, s.x, t.x), 0.f);
    r.y = fmaxf(fmaf(z.y, s.y, t.y), 0.f);
    r.z = fmaxf(fmaf(z.z, s.z, t.z), 0.f);
    r.w = fmaxf(fmaf(z.w, s.w, t.w), 0.f);
    *reinterpret_cast<float4*>(&out[idx]) = r;
}

// ---------------- launch ----------------------------------------------------
extern "C" void kernel_launch(void* const* d_in, const int* in_sizes, int n_in,
                              void* d_out, int out_size)
{
    const float* x   = (const float*)d_in[0];
    const float* sp  = (const float*)d_in[1];   // ste_previous
    const float* sf  = (const float*)d_in[2];   // ste_future
    const float* Wq  = (const float*)d_in[3];
    const float* bq  = (const float*)d_in[4];
    const float* gq  = (const float*)d_in[5];
    const float* beq = (const float*)d_in[6];
    const float* Wk  = (const float*)d_in[7];
    const float* bk  = (const float*)d_in[8];
    const float* gk  = (const float*)d_in[9];
    const float* bek = (const float*)d_in[10];
    const float* Wv  = (const float*)d_in[11];
    const float* bv  = (const float*)d_in[12];
    const float* gv  = (const float*)d_in[13];
    const float* bev = (const float*)d_in[14];
    const float* Wo  = (const float*)d_in[15];
    const float* bo  = (const float*)d_in[16];
    const float* go  = (const float*)d_in[17];
    const float* beo = (const float*)d_in[18];
    float* out = (float*)d_out;

    float *Yq, *Yk, *Yv, *O;
    cudaGetSymbolAddress((void**)&Yq, g_bufQ);
    cudaGetSymbolAddress((void**)&Yk, g_bufK);
    cudaGetSymbolAddress((void**)&Yv, g_bufV);
    cudaGetSymbolAddress((void**)&O,  g_bufO);

    const int gemm_blocks = (MROWS / 64) * (DDIM / 64);  // 7800

    zero_stats_kernel<<<1, 256>>>();

    gemm_bn_kernel<<<gemm_blocks, 256>>>(sf, Wq, bq, Yq, 0);
    gemm_bn_kernel<<<gemm_blocks, 256>>>(sp, Wk, bk, Yk, 1);
    gemm_bn_kernel<<<gemm_blocks, 256>>>(x,  Wv, bv, Yv, 2);

    finalize_bn_kernel<<<1, 256>>>(gq, beq, 0);
    finalize_bn_kernel<<<1, 256>>>(gk, bek, 1);
    finalize_bn_kernel<<<1, 256>>>(gv, bev, 2);

    attn_kernel<<<BB * NN * 2, 256>>>(Yq, Yk, Yv, O);

    gemm_bn_kernel<<<gemm_blocks, 256>>>(O, Wo, bo, Yq, 3);  // reuse Yq as Z
    finalize_bn_kernel<<<1, 256>>>(go, beo, 3);

    norm_out_kernel<<<(MROWS * DDIM) / (4 * 256), 256>>>(Yq, out);
}

// round 3
// speedup vs baseline: 2.0241x; 2.0241x over previous
#include <cuda_runtime.h>

#define BB 16
#define LL 24
#define NN 325
#define DDIM 256
#define HH 8
#define MROWS (BB*LL*NN)   // 124800, divisible by 128

typedef unsigned long long ULL;

// ---------------- scratch (device globals; no cudaMalloc allowed) ----------
__device__ float g_bufQ[MROWS * DDIM];
__device__ float g_bufK[MROWS * DDIM];
__device__ float g_bufV[MROWS * DDIM];
__device__ float g_bufO[MROWS * DDIM];

__device__ __align__(16) float g_sum[4][DDIM];
__device__ __align__(16) float g_sumsq[4][DDIM];
__device__ __align__(16) float g_scale[4][DDIM];
__device__ __align__(16) float g_shift[4][DDIM];

// ---------------- f32x2 packed math helpers --------------------------------
__device__ __forceinline__ ULL pack2(float x, float y) {
    ULL r;
    asm("mov.b64 %0, {%1, %2};" : "=l"(r) : "f"(x), "f"(y));
    return r;
}
__device__ __forceinline__ ULL fma2(ULL a, ULL b, ULL c) {
    ULL d;
    asm("fma.rn.f32x2 %0, %1, %2, %3;" : "=l"(d) : "l"(a), "l"(b), "l"(c));
    return d;
}
__device__ __forceinline__ float2 unpack2(ULL v) {
    float2 r;
    asm("mov.b64 {%0, %1}, %2;" : "=f"(r.x), "=f"(r.y) : "l"(v));
    return r;
}

// ---------------- zero the BN stat accumulators (every launch) -------------
__global__ void zero_stats_kernel() {
    int t = threadIdx.x;  // 256 threads
#pragma unroll
    for (int s = 0; s < 4; s++) {
        g_sum[s][t] = 0.f;
        g_sumsq[s][t] = 0.f;
    }
}

// ---------------- GEMM (M x 256) * (256 x 256) + bias, with BN stats -------
// Tile 128(M) x 128(N) x 16(K), 256 threads, 8x8 micro-tile per thread.
// Columns per thread: [tx*4 .. tx*4+3] and [64+tx*4 .. 64+tx*4+3]
// (contiguous float4 groups -> conflict-free W smem reads).
__global__ __launch_bounds__(256, 2) void gemm_bn_kernel(
    const float* __restrict__ X, const float* __restrict__ W,
    const float* __restrict__ bias, float* __restrict__ Y, int set)
{
    __shared__ float Xs[16][132];   // [k][m], pad 4 (132%32=4 -> STS 2-way max)
    __shared__ float Ws[16][128];   // [k][n]
    __shared__ float s_sum[128], s_sq[128];

    const int tid = threadIdx.x;
    const int tx = tid & 15;       // col group
    const int ty = tid >> 4;       // row group
    const int bm = blockIdx.x >> 1;        // 0..974
    const int bn = blockIdx.x & 1;         // 0..1
    const int m0 = bm * 128, n0 = bn * 128;

    if (tid < 128) { s_sum[tid] = 0.f; s_sq[tid] = 0.f; }

    ULL acc[8][4];
#pragma unroll
    for (int i = 0; i < 8; i++)
#pragma unroll
        for (int j = 0; j < 4; j++) acc[i][j] = 0ull;

    // load mapping
    const int xrow = tid >> 2;            // 0..63 (and +64)
    const int xk4  = (tid & 3) << 2;      // 0,4,8,12
    const int wrow = tid >> 4;            // 0..15
    const int wc4  = (tid & 15) << 2;     // 0..60 (and +64)

    const float* Xp0 = X + (size_t)(m0 + xrow) * DDIM + xk4;
    const float* Xp1 = Xp0 + (size_t)64 * DDIM;
    const float* Wp  = W + (size_t)wrow * DDIM + n0 + wc4;

    for (int k0 = 0; k0 < DDIM; k0 += 16) {
        float4 xa = *reinterpret_cast<const float4*>(Xp0 + k0);
        float4 xb = *reinterpret_cast<const float4*>(Xp1 + k0);
        float4 wv0 = *reinterpret_cast<const float4*>(Wp + (size_t)k0 * DDIM);
        float4 wv1 = *reinterpret_cast<const float4*>(Wp + (size_t)k0 * DDIM + 64);
        Xs[xk4 + 0][xrow] = xa.x;
        Xs[xk4 + 1][xrow] = xa.y;
        Xs[xk4 + 2][xrow] = xa.z;
        Xs[xk4 + 3][xrow] = xa.w;
        Xs[xk4 + 0][xrow + 64] = xb.x;
        Xs[xk4 + 1][xrow + 64] = xb.y;
        Xs[xk4 + 2][xrow + 64] = xb.z;
        Xs[xk4 + 3][xrow + 64] = xb.w;
        *reinterpret_cast<float4*>(&Ws[wrow][wc4])      = wv0;
        *reinterpret_cast<float4*>(&Ws[wrow][wc4 + 64]) = wv1;
        __syncthreads();
#pragma unroll
        for (int k = 0; k < 16; k++) {
            float4 r0 = *reinterpret_cast<const float4*>(&Xs[k][ty << 3]);
            float4 r1 = *reinterpret_cast<const float4*>(&Xs[k][(ty << 3) + 4]);
            const ULL* wp0 = reinterpret_cast<const ULL*>(&Ws[k][tx << 2]);
            const ULL* wp1 = reinterpret_cast<const ULL*>(&Ws[k][(tx << 2) + 64]);
            ULL w0 = wp0[0], w1 = wp0[1];
            ULL w2 = wp1[0], w3 = wp1[1];
            ULL xd;
            xd = pack2(r0.x, r0.x);
            acc[0][0] = fma2(xd, w0, acc[0][0]); acc[0][1] = fma2(xd, w1, acc[0][1]);
            acc[0][2] = fma2(xd, w2, acc[0][2]); acc[0][3] = fma2(xd, w3, acc[0][3]);
            xd = pack2(r0.y, r0.y);
            acc[1][0] = fma2(xd, w0, acc[1][0]); acc[1][1] = fma2(xd, w1, acc[1][1]);
            acc[1][2] = fma2(xd, w2, acc[1][2]); acc[1][3] = fma2(xd, w3, acc[1][3]);
            xd = pack2(r0.z, r0.z);
            acc[2][0] = fma2(xd, w0, acc[2][0]); acc[2][1] = fma2(xd, w1, acc[2][1]);
            acc[2][2] = fma2(xd, w2, acc[2][2]); acc[2][3] = fma2(xd, w3, acc[2][3]);
            xd = pack2(r0.w, r0.w);
            acc[3][0] = fma2(xd, w0, acc[3][0]); acc[3][1] = fma2(xd, w1, acc[3][1]);
            acc[3][2] = fma2(xd, w2, acc[3][2]); acc[3][3] = fma2(xd, w3, acc[3][3]);
            xd = pack2(r1.x, r1.x);
            acc[4][0] = fma2(xd, w0, acc[4][0]); acc[4][1] = fma2(xd, w1, acc[4][1]);
            acc[4][2] = fma2(xd, w2, acc[4][2]); acc[4][3] = fma2(xd, w3, acc[4][3]);
            xd = pack2(r1.y, r1.y);
            acc[5][0] = fma2(xd, w0, acc[5][0]); acc[5][1] = fma2(xd, w1, acc[5][1]);
            acc[5][2] = fma2(xd, w2, acc[5][2]); acc[5][3] = fma2(xd, w3, acc[5][3]);
            xd = pack2(r1.z, r1.z);
            acc[6][0] = fma2(xd, w0, acc[6][0]); acc[6][1] = fma2(xd, w1, acc[6][1]);
            acc[6][2] = fma2(xd, w2, acc[6][2]); acc[6][3] = fma2(xd, w3, acc[6][3]);
            xd = pack2(r1.w, r1.w);
            acc[7][0] = fma2(xd, w0, acc[7][0]); acc[7][1] = fma2(xd, w1, acc[7][1]);
            acc[7][2] = fma2(xd, w2, acc[7][2]); acc[7][3] = fma2(xd, w3, acc[7][3]);
        }
        __syncthreads();
    }

    // epilogue: bias, store, per-channel stats
    const int c0 = n0 + (tx << 2);        // cols c0..c0+3
    const int c1 = c0 + 64;               // cols c1..c1+3
    float4 bz0 = *reinterpret_cast<const float4*>(&bias[c0]);
    float4 bz1 = *reinterpret_cast<const float4*>(&bias[c1]);
    float csum[8] = {0,0,0,0,0,0,0,0};
    float csq[8]  = {0,0,0,0,0,0,0,0};
#pragma unroll
    for (int r = 0; r < 8; r++) {
        float2 p0 = unpack2(acc[r][0]);
        float2 p1 = unpack2(acc[r][1]);
        float2 p2 = unpack2(acc[r][2]);
        float2 p3 = unpack2(acc[r][3]);
        float y0 = p0.x + bz0.x, y1 = p0.y + bz0.y;
        float y2 = p1.x + bz0.z, y3 = p1.y + bz0.w;
        float y4 = p2.x + bz1.x, y5 = p2.y + bz1.y;
        float y6 = p3.x + bz1.z, y7 = p3.y + bz1.w;
        size_t rowoff = (size_t)(m0 + (ty << 3) + r) * DDIM;
        *reinterpret_cast<float4*>(&Y[rowoff + c0]) = make_float4(y0, y1, y2, y3);
        *reinterpret_cast<float4*>(&Y[rowoff + c1]) = make_float4(y4, y5, y6, y7);
        csum[0] += y0; csq[0] += y0 * y0;
        csum[1] += y1; csq[1] += y1 * y1;
        csum[2] += y2; csq[2] += y2 * y2;
        csum[3] += y3; csq[3] += y3 * y3;
        csum[4] += y4; csq[4] += y4 * y4;
        csum[5] += y5; csq[5] += y5 * y5;
        csum[6] += y6; csq[6] += y6 * y6;
        csum[7] += y7; csq[7] += y7 * y7;
    }
#pragma unroll
    for (int j = 0; j < 4; j++) {
        atomicAdd(&s_sum[(tx << 2) + j], csum[j]);
        atomicAdd(&s_sq[(tx << 2) + j], csq[j]);
        atomicAdd(&s_sum[(tx << 2) + 64 + j], csum[4 + j]);
        atomicAdd(&s_sq[(tx << 2) + 64 + j], csq[4 + j]);
    }
    __syncthreads();
    if (tid < 128) {
        atomicAdd(&g_sum[set][n0 + tid], s_sum[tid]);
        atomicAdd(&g_sumsq[set][n0 + tid], s_sq[tid]);
    }
}

// ---------------- finalize BN: per-channel scale/shift ---------------------
__global__ void finalize_bn_kernel(const float* __restrict__ gamma,
                                   const float* __restrict__ beta, int set) {
    int o = threadIdx.x;  // 256
    const float invM = 1.f / (float)MROWS;
    float mu  = g_sum[set][o] * invM;
    float var = g_sumsq[set][o] * invM - mu * mu;
    float sc = gamma[o] * rsqrtf(var + 1e-5f);
    g_scale[set][o] = sc;
    g_shift[set][o] = beta[o] - mu * sc;
}

// ---------------- attention ------------------------------------------------
// One block per (b, n, chunk-half), 384 threads. Vectorized (float4) loads of
// q/k/v with BN+ReLU applied on the fly; then exactly one (chunk, lf) task
// per thread: 24-wide softmax, 8-dim output.
__device__ __forceinline__ float4 norm_relu4(float4 y, float4 s, float4 t) {
    float4 r;
    r.x = fmaxf(fmaf(y.x, s.x, t.x), 0.f);
    r.y = fmaxf(fmaf(y.y, s.y, t.y), 0.f);
    r.z = fmaxf(fmaf(y.z, s.z, t.z), 0.f);
    r.w = fmaxf(fmaf(y.w, s.w, t.w), 0.f);
    return r;
}

__global__ __launch_bounds__(384) void attn_kernel(
    const float* __restrict__ Yq, const float* __restrict__ Yk,
    const float* __restrict__ Yv, float* __restrict__ O)
{
    __shared__ float qs[16 * 196];
    __shared__ float ks[16 * 196];
    __shared__ float vs[16 * 196];

    const int blk  = blockIdx.x;       // 0..10399
    const int half = blk & 1;
    const int pair = blk >> 1;         // 0..5199
    const int b = pair / NN;
    const int n = pair % NN;
    const int dbase = half * 128;

    // 768 float4 per tensor; 384 threads -> 2 each
    for (int f = threadIdx.x; f < LL * 32; f += 384) {
        int l   = f >> 5;               // 0..23
        int q4  = f & 31;               // float4 index within 128-d row
        int dd0 = q4 << 2;              // 0..124, multiple of 4
        int c   = dd0 >> 3;
        int h0  = dd0 & 7;              // 0 or 4
        int so  = c * 196 + l * 8 + h0; // multiple of 4 -> float4-aligned
        int d0  = dbase + dd0;
        size_t g = ((size_t)(b * LL + l) * NN + n) * DDIM + d0;

        float4 sq = *reinterpret_cast<const float4*>(&g_scale[0][d0]);
        float4 tq = *reinterpret_cast<const float4*>(&g_shift[0][d0]);
        float4 sk = *reinterpret_cast<const float4*>(&g_scale[1][d0]);
        float4 tk = *reinterpret_cast<const float4*>(&g_shift[1][d0]);
        float4 sv = *reinterpret_cast<const float4*>(&g_scale[2][d0]);
        float4 tv = *reinterpret_cast<const float4*>(&g_shift[2][d0]);

        float4 yq = *reinterpret_cast<const float4*>(&Yq[g]);
        float4 yk = *reinterpret_cast<const float4*>(&Yk[g]);
        float4 yv = *reinterpret_cast<const float4*>(&Yv[g]);

        *reinterpret_cast<float4*>(&qs[so]) = norm_relu4(yq, sq, tq);
        *reinterpret_cast<float4*>(&ks[so]) = norm_relu4(yk, sk, tk);
        *reinterpret_cast<float4*>(&vs[so]) = norm_relu4(yv, sv, tv);
    }
    __syncthreads();

    const float inv_scale = 0.17677669529663687f;  // 1/sqrt(32)

    const int task = threadIdx.x;      // exactly 16*24 = 384 tasks
    const int c  = task & 15;
    const int lf = task >> 4;
    const float* qr = &qs[c * 196 + lf * 8];
    float4 q0 = *reinterpret_cast<const float4*>(qr);
    float4 q1 = *reinterpret_cast<const float4*>(qr + 4);

    float sc[24];
    float mx = -1e30f;
#pragma unroll
    for (int p = 0; p < 24; p++) {
        const float* kr = &ks[c * 196 + p * 8];
        float4 k0 = *reinterpret_cast<const float4*>(kr);
        float4 k1 = *reinterpret_cast<const float4*>(kr + 4);
        float s = q0.x * k0.x + q0.y * k0.y + q0.z * k0.z + q0.w * k0.w +
                  q1.x * k1.x + q1.y * k1.y + q1.z * k1.z + q1.w * k1.w;
        s *= inv_scale;
        sc[p] = s;
        mx = fmaxf(mx, s);
    }
    float ssum = 0.f;
#pragma unroll
    for (int p = 0; p < 24; p++) {
        float e = __expf(sc[p] - mx);
        sc[p] = e;
        ssum += e;
    }
    float inv = 1.f / ssum;
    float o[8] = {0.f, 0.f, 0.f, 0.f, 0.f, 0.f, 0.f, 0.f};
#pragma unroll
    for (int p = 0; p < 24; p++) {
        float a = sc[p] * inv;
        const float* vr = &vs[c * 196 + p * 8];
        float4 v0 = *reinterpret_cast<const float4*>(vr);
        float4 v1 = *reinterpret_cast<const float4*>(vr + 4);
        o[0] = fmaf(a, v0.x, o[0]);
        o[1] = fmaf(a, v0.y, o[1]);
        o[2] = fmaf(a, v0.z, o[2]);
        o[3] = fmaf(a, v0.w, o[3]);
        o[4] = fmaf(a, v1.x, o[4]);
        o[5] = fmaf(a, v1.y, o[5]);
        o[6] = fmaf(a, v1.z, o[6]);
        o[7] = fmaf(a, v1.w, o[7]);
    }
    size_t g = ((size_t)(b * LL + lf) * NN + n) * DDIM + dbase + c * 8;
    *reinterpret_cast<float4*>(&O[g])     = make_float4(o[0], o[1], o[2], o[3]);
    *reinterpret_cast<float4*>(&O[g + 4]) = make_float4(o[4], o[5], o[6], o[7]);
}

// ---------------- final normalize + relu -> d_out --------------------------
__global__ __launch_bounds__(256) void norm_out_kernel(
    const float* __restrict__ Z, float* __restrict__ out)
{
    size_t i = (size_t)blockIdx.x * 256 + threadIdx.x;  // one float4 each
    size_t idx = i * 4;
    int d = (int)(idx & 255);
    float4 z = *reinterpret_cast<const float4*>(&Z[idx]);
    float4 s = *reinterpret_cast<const float4*>(&g_scale[3][d]);
    float4 t = *reinterpret_cast<const float4*>(&g_shift[3][d]);
    float4 r;
    r.x = fmaxf(fmaf(z.x, s.x, t.x), 0.f);
    r.y = fmaxf(fmaf(z.y, s.y, t.y), 0.f);
    r.z = fmaxf(fmaf(z.z, s.z, t.z), 0.f);
    r.w = fmaxf(fmaf(z.w, s.w, t.w), 0.f);
    *reinterpret_cast<float4*>(&out[idx]) = r;
}

// ---------------- launch ----------------------------------------------------
extern "C" void kernel_launch(void* const* d_in, const int* in_sizes, int n_in,
                              void* d_out, int out_size)
{
    const float* x   = (const float*)d_in[0];
    const float* sp  = (const float*)d_in[1];   // ste_previous
    const float* sf  = (const float*)d_in[2];   // ste_future
    const float* Wq  = (const float*)d_in[3];
    const float* bq  = (const float*)d_in[4];
    const float* gq  = (const float*)d_in[5];
    const float* beq = (const float*)d_in[6];
    const float* Wk  = (const float*)d_in[7];
    const float* bk  = (const float*)d_in[8];
    const float* gk  = (const float*)d_in[9];
    const float* bek = (const float*)d_in[10];
    const float* Wv  = (const float*)d_in[11];
    const float* bv  = (const float*)d_in[12];
    const float* gv  = (const float*)d_in[13];
    const float* bev = (const float*)d_in[14];
    const float* Wo  = (const float*)d_in[15];
    const float* bo  = (const float*)d_in[16];
    const float* go  = (const float*)d_in[17];
    const float* beo = (const float*)d_in[18];
    float* out = (float*)d_out;

    float *Yq, *Yk, *Yv, *O;
    cudaGetSymbolAddress((void**)&Yq, g_bufQ);
    cudaGetSymbolAddress((void**)&Yk, g_bufK);
    cudaGetSymbolAddress((void**)&Yv, g_bufV);
    cudaGetSymbolAddress((void**)&O,  g_bufO);

    const int gemm_blocks = (MROWS / 128) * (DDIM / 128);  // 1950

    zero_stats_kernel<<<1, 256>>>();

    gemm_bn_kernel<<<gemm_blocks, 256>>>(sf, Wq, bq, Yq, 0);
    gemm_bn_kernel<<<gemm_blocks, 256>>>(sp, Wk, bk, Yk, 1);
    gemm_bn_kernel<<<gemm_blocks, 256>>>(x,  Wv, bv, Yv, 2);

    finalize_bn_kernel<<<1, 256>>>(gq, beq, 0);
    finalize_bn_kernel<<<1, 256>>>(gk, bek, 1);
    finalize_bn_kernel<<<1, 256>>>(gv, bev, 2);

    attn_kernel<<<BB * NN * 2, 384>>>(Yq, Yk, Yv, O);

    gemm_bn_kernel<<<gemm_blocks, 256>>>(O, Wo, bo, Yq, 3);  // reuse Yq as Z
    finalize_bn_kernel<<<1, 256>>>(go, beo, 3);

    norm_out_kernel<<<(MROWS * DDIM) / (4 * 256), 256>>>(Yq, out);
}

// round 5
// speedup vs baseline: 3.3235x; 1.6420x over previous
#include <cuda_runtime.h>
#include <cstdint>

#define BB 16
#define LL 24
#define NN 325
#define DDIM 256
#define MROWS (BB*LL*NN)   // 124800 = 975 * 128

typedef unsigned long long ULL;

// ---------------- scratch (device globals) ---------------------------------
__device__ float g_bufQ[MROWS * DDIM];
__device__ float g_bufK[MROWS * DDIM];
__device__ float g_bufV[MROWS * DDIM];
__device__ float g_bufO[MROWS * DDIM];

__device__ unsigned short g_Whi[4][DDIM * DDIM];   // [o][k] bf16, transposed
__device__ unsigned short g_Wlo[4][DDIM * DDIM];

__device__ __align__(16) float g_sum[4][DDIM];
__device__ __align__(16) float g_sumsq[4][DDIM];
__device__ __align__(16) float g_scale[4][DDIM];
__device__ __align__(16) float g_shift[4][DDIM];

// ---------------- helpers ----------------------------------------------------
__device__ __forceinline__ uint32_t smem_u32(const void* p) {
    uint32_t a;
    asm("{ .reg .u64 t; cvta.to.shared.u64 t, %1; cvt.u32.u64 %0, t; }"
        : "=r"(a) : "l"(p));
    return a;
}
// packs: upper half = bf16(hiArg), lower half = bf16(loArg)
__device__ __forceinline__ uint32_t cvt2bf(float lo, float hi) {
    uint32_t r;
    asm("cvt.rn.bf16x2.f32 %0, %1, %2;" : "=r"(r) : "f"(hi), "f"(lo));
    return r;
}
__device__ __forceinline__ void ldsm4(uint32_t* r, uint32_t addr) {
    asm volatile("ldmatrix.sync.aligned.m8n8.x4.shared.b16 {%0,%1,%2,%3}, [%4];"
        : "=r"(r[0]), "=r"(r[1]), "=r"(r[2]), "=r"(r[3]) : "r"(addr));
}
__device__ __forceinline__ void mma_bf16(float* c, const uint32_t* a,
                                         uint32_t b0, uint32_t b1) {
    asm volatile(
        "mma.sync.aligned.m16n8k16.row.col.f32.bf16.bf16.f32 "
        "{%0,%1,%2,%3}, {%4,%5,%6,%7}, {%8,%9}, {%0,%1,%2,%3};"
        : "+f"(c[0]), "+f"(c[1]), "+f"(c[2]), "+f"(c[3])
        : "r"(a[0]), "r"(a[1]), "r"(a[2]), "r"(a[3]), "r"(b0), "r"(b1));
}

// ---------------- zero the BN stat accumulators -----------------------------
__global__ void zero_stats_kernel() {
    int t = threadIdx.x;
#pragma unroll
    for (int s = 0; s < 4; s++) { g_sum[s][t] = 0.f; g_sumsq[s][t] = 0.f; }
}

// ---------------- W convert: fp32 [k][o] -> bf16 hi/lo [o][k] ---------------
__global__ void conv_w_kernel(const float* __restrict__ W,
                              unsigned short* __restrict__ hi,
                              unsigned short* __restrict__ lo) {
    int idx = blockIdx.x * 256 + threadIdx.x;   // grid 64 -> 16384 threads
#pragma unroll
    for (int i = 0; i < 4; i++) {
        int e = idx + i * 16384;                // 65536 elements, [o][k] linear
        int o = e >> 8, k = e & 255;
        float x = W[k * 256 + o];
        unsigned short h;
        asm("cvt.rn.bf16.f32 %0, %1;" : "=h"(h) : "f"(x));
        float fh = __uint_as_float(((uint32_t)h) << 16);
        unsigned short l;
        float res = x - fh;
        asm("cvt.rn.bf16.f32 %0, %1;" : "=h"(l) : "f"(res));
        hi[e] = h;
        lo[e] = l;
    }
}

// ---------------- HMMA bf16x3 GEMM + bias + BN stats -------------------------
// C[m,o] = sum_k X[m,k] W[k,o] + b[o]
// Block: 128(M) x 128(N), 8 warps (4 M-warps x 2 N-warps), warp = 32x64.
// K processed in 4 chunks of 64 bf16; A converted fp32->bf16 hi/lo on the fly.
// Smem tiles 128 rows x 64 bf16 (128B rows) with SW128 xor swizzle.
#define SM_BIAS 0
#define SM_SUM  1024
#define SM_SQ   1536
#define SM_AH   2048
#define SM_AL   (SM_AH + 16384)
#define SM_BH   (SM_AL + 16384)
#define SM_BL   (SM_BH + 16384)
#define SM_TOT  (SM_BL + 16384)    // 67584 bytes

__global__ __launch_bounds__(256, 2) void gemm_mma_kernel(
    const float* __restrict__ X,
    const unsigned short* __restrict__ whi,
    const unsigned short* __restrict__ wlo,
    const float* __restrict__ bias, float* __restrict__ Y, int set)
{
    extern __shared__ char smem[];
    const uint32_t sb = smem_u32(smem);
    const int tid  = threadIdx.x;
    const int wid  = tid >> 5, lane = tid & 31;
    const int bm   = blockIdx.x >> 1;
    const int bn   = blockIdx.x & 1;
    const int m0   = bm * 128;
    const int n0g  = bn * 128;
    const int warp_m = wid & 3;      // 0..3 -> M offset *32
    const int warp_n = wid >> 2;     // 0..1 -> N offset *64

    float* bias_s = (float*)(smem + SM_BIAS);
    float* sum_s  = (float*)(smem + SM_SUM);
    float* sq_s   = (float*)(smem + SM_SQ);
    if (tid < 128) {
        bias_s[tid] = bias[n0g + tid];
        sum_s[tid] = 0.f;
        sq_s[tid]  = 0.f;
    }

    float acc[2][8][4];
#pragma unroll
    for (int a = 0; a < 2; a++)
#pragma unroll
        for (int b = 0; b < 8; b++)
#pragma unroll
            for (int c = 0; c < 4; c++) acc[a][b][c] = 0.f;

    // per-lane ldmatrix address components
    const uint32_t swz = (lane & 7) << 4;
    const int a_row = (warp_m * 32) + (lane & 7) + ((lane >> 3) & 1) * 8;
    const int a_kof = (lane >> 4) * 16;
    const int b_row = (warp_n * 64) + (lane & 7) + ((lane >> 4) & 1) * 8;
    const int b_kof = ((lane >> 3) & 1) * 16;
    const uint32_t aH = sb + SM_AH + a_row * 128;
    const uint32_t aL = sb + SM_AL + a_row * 128;
    const uint32_t bH = sb + SM_BH + b_row * 128;
    const uint32_t bL = sb + SM_BL + b_row * 128;

    for (int kc = 0; kc < 4; kc++) {
        const int k0 = kc * 64;
        // ---- A fill: 128 rows x 64 k, fp32 -> bf16 hi/lo ----
#pragma unroll
        for (int i = 0; i < 4; i++) {
            int task = tid + (i << 8);          // 1024 tasks = 128 rows * 8 segs
            int r = task >> 3, seg = task & 7;
            const float4* xp = reinterpret_cast<const float4*>(
                &X[(size_t)(m0 + r) * 256 + k0 + seg * 8]);
            float4 x0 = xp[0], x1 = xp[1];
            uint32_t h01 = cvt2bf(x0.x, x0.y);
            uint32_t h23 = cvt2bf(x0.z, x0.w);
            uint32_t h45 = cvt2bf(x1.x, x1.y);
            uint32_t h67 = cvt2bf(x1.z, x1.w);
            float f0 = __uint_as_float(h01 << 16);
            float f1 = __uint_as_float(h01 & 0xFFFF0000u);
            float f2 = __uint_as_float(h23 << 16);
            float f3 = __uint_as_float(h23 & 0xFFFF0000u);
            float f4 = __uint_as_float(h45 << 16);
            float f5 = __uint_as_float(h45 & 0xFFFF0000u);
            float f6 = __uint_as_float(h67 << 16);
            float f7 = __uint_as_float(h67 & 0xFFFF0000u);
            uint32_t l01 = cvt2bf(x0.x - f0, x0.y - f1);
            uint32_t l23 = cvt2bf(x0.z - f2, x0.w - f3);
            uint32_t l45 = cvt2bf(x1.x - f4, x1.y - f5);
            uint32_t l67 = cvt2bf(x1.z - f6, x1.w - f7);
            int off = r * 128 + ((seg * 16) ^ ((r & 7) << 4));
            *reinterpret_cast<uint4*>(smem + SM_AH + off) =
                make_uint4(h01, h23, h45, h67);
            *reinterpret_cast<uint4*>(smem + SM_AL + off) =
                make_uint4(l01, l23, l45, l67);
        }
        // ---- B fill: 128 n-rows x 64 k, bf16 hi/lo pre-converted ----
#pragma unroll
        for (int i = 0; i < 8; i++) {
            int task = tid + (i << 8);          // 2048
            int half = task >> 10;
            int rem  = task & 1023;
            int r = rem >> 3, seg = rem & 7;
            const unsigned short* src = half ? wlo : whi;
            uint4 v = *reinterpret_cast<const uint4*>(
                &src[(size_t)(n0g + r) * 256 + k0 + seg * 8]);
            int off = r * 128 + ((seg * 16) ^ ((r & 7) << 4));
            *reinterpret_cast<uint4*>(smem + (half ? SM_BL : SM_BH) + off) = v;
        }
        __syncthreads();

        // ---- MMA: 4 k16 steps ----
#pragma unroll
        for (int ks = 0; ks < 4; ks++) {
            const int kb = ks * 32;
            uint32_t ah[2][4], al[2][4];
#pragma unroll
            for (int mi = 0; mi < 2; mi++) {
                uint32_t ko = (uint32_t)(kb + a_kof) ^ swz;
                ldsm4(ah[mi], aH + mi * (16 * 128) + ko);
                ldsm4(al[mi], aL + mi * (16 * 128) + ko);
            }
#pragma unroll
            for (int g = 0; g < 4; g++) {
                uint32_t bh[4], bl[4];
                uint32_t ko = (uint32_t)(kb + b_kof) ^ swz;
                ldsm4(bh, bH + g * (16 * 128) + ko);
                ldsm4(bl, bL + g * (16 * 128) + ko);
#pragma unroll
                for (int mi = 0; mi < 2; mi++) {
                    mma_bf16(acc[mi][2 * g],     ah[mi], bh[0], bh[1]);
                    mma_bf16(acc[mi][2 * g],     al[mi], bh[0], bh[1]);
                    mma_bf16(acc[mi][2 * g],     ah[mi], bl[0], bl[1]);
                    mma_bf16(acc[mi][2 * g + 1], ah[mi], bh[2], bh[3]);
                    mma_bf16(acc[mi][2 * g + 1], al[mi], bh[2], bh[3]);
                    mma_bf16(acc[mi][2 * g + 1], ah[mi], bl[2], bl[3]);
                }
            }
        }
        __syncthreads();
    }

    // ---- epilogue: bias, store, BN stats ----
    const int qrow = lane >> 2;           // 0..7
    const int qcol = (lane & 3) * 2;      // 0,2,4,6
#pragma unroll
    for (int g = 0; g < 4; g++) {
#pragma unroll
        for (int sub = 0; sub < 2; sub++) {
            const int ncol = warp_n * 64 + g * 16 + sub * 8 + qcol;  // 0..127
            const float b0 = bias_s[ncol], b1 = bias_s[ncol + 1];
            float p0 = 0.f, p1 = 0.f, q0 = 0.f, q1 = 0.f;
#pragma unroll
            for (int mi = 0; mi < 2; mi++) {
                const float* a = acc[mi][2 * g + sub];
                float y00 = a[0] + b0, y01 = a[1] + b1;
                float y10 = a[2] + b0, y11 = a[3] + b1;
                const int r = m0 + warp_m * 32 + mi * 16 + qrow;
                *reinterpret_cast<float2*>(&Y[(size_t)r * 256 + n0g + ncol]) =
                    make_float2(y00, y01);
                *reinterpret_cast<float2*>(&Y[(size_t)(r + 8) * 256 + n0g + ncol]) =
                    make_float2(y10, y11);
                p0 += y00 + y10;
                p1 += y01 + y11;
                q0 += y00 * y00 + y10 * y10;
                q1 += y01 * y01 + y11 * y11;
            }
#pragma unroll
            for (int d = 4; d < 32; d <<= 1) {
                p0 += __shfl_xor_sync(0xffffffffu, p0, d);
                p1 += __shfl_xor_sync(0xffffffffu, p1, d);
                q0 += __shfl_xor_sync(0xffffffffu, q0, d);
                q1 += __shfl_xor_sync(0xffffffffu, q1, d);
            }
            if (lane < 4) {
                atomicAdd(&sum_s[ncol], p0);
                atomicAdd(&sum_s[ncol + 1], p1);
                atomicAdd(&sq_s[ncol], q0);
                atomicAdd(&sq_s[ncol + 1], q1);
            }
        }
    }
    __syncthreads();
    if (tid < 128) {
        atomicAdd(&g_sum[set][n0g + tid], sum_s[tid]);
        atomicAdd(&g_sumsq[set][n0g + tid], sq_s[tid]);
    }
}

// ---------------- finalize BN ------------------------------------------------
__global__ void finalize_bn_kernel(const float* __restrict__ gamma,
                                   const float* __restrict__ beta, int set) {
    int o = threadIdx.x;
    const float invM = 1.f / (float)MROWS;
    float mu  = g_sum[set][o] * invM;
    float var = g_sumsq[set][o] * invM - mu * mu;
    float sc = gamma[o] * rsqrtf(var + 1e-5f);
    g_scale[set][o] = sc;
    g_shift[set][o] = beta[o] - mu * sc;
}

// ---------------- attention --------------------------------------------------
__device__ __forceinline__ float4 norm_relu4(float4 y, float4 s, float4 t) {
    float4 r;
    r.x = fmaxf(fmaf(y.x, s.x, t.x), 0.f);
    r.y = fmaxf(fmaf(y.y, s.y, t.y), 0.f);
    r.z = fmaxf(fmaf(y.z, s.z, t.z), 0.f);
    r.w = fmaxf(fmaf(y.w, s.w, t.w), 0.f);
    return r;
}

__global__ __launch_bounds__(384) void attn_kernel(
    const float* __restrict__ Yq, const float* __restrict__ Yk,
    const float* __restrict__ Yv, float* __restrict__ O)
{
    __shared__ float qs[16 * 196];
    __shared__ float ks[16 * 196];
    __shared__ float vs[16 * 196];

    const int blk  = blockIdx.x;
    const int half = blk & 1;
    const int pair = blk >> 1;
    const int b = pair / NN;
    const int n = pair % NN;
    const int dbase = half * 128;

    for (int f = threadIdx.x; f < LL * 32; f += 384) {
        int l   = f >> 5;
        int q4  = f & 31;
        int dd0 = q4 << 2;
        int c   = dd0 >> 3;
        int h0  = dd0 & 7;
        int so  = c * 196 + l * 8 + h0;
        int d0  = dbase + dd0;
        size_t g = ((size_t)(b * LL + l) * NN + n) * DDIM + d0;

        float4 sq = *reinterpret_cast<const float4*>(&g_scale[0][d0]);
        float4 tq = *reinterpret_cast<const float4*>(&g_shift[0][d0]);
        float4 sk = *reinterpret_cast<const float4*>(&g_scale[1][d0]);
        float4 tk = *reinterpret_cast<const float4*>(&g_shift[1][d0]);
        float4 sv = *reinterpret_cast<const float4*>(&g_scale[2][d0]);
        float4 tv = *reinterpret_cast<const float4*>(&g_shift[2][d0]);

        float4 yq = *reinterpret_cast<const float4*>(&Yq[g]);
        float4 yk = *reinterpret_cast<const float4*>(&Yk[g]);
        float4 yv = *reinterpret_cast<const float4*>(&Yv[g]);

        *reinterpret_cast<float4*>(&qs[so]) = norm_relu4(yq, sq, tq);
        *reinterpret_cast<float4*>(&ks[so]) = norm_relu4(yk, sk, tk);
        *reinterpret_cast<float4*>(&vs[so]) = norm_relu4(yv, sv, tv);
    }
    __syncthreads();

    const float inv_scale = 0.17677669529663687f;  // 1/sqrt(32)

    const int task = threadIdx.x;
    const int c  = task & 15;
    const int lf = task >> 4;
    const float* qr = &qs[c * 196 + lf * 8];
    float4 q0 = *reinterpret_cast<const float4*>(qr);
    float4 q1 = *reinterpret_cast<const float4*>(qr + 4);

    float sc[24];
    float mx = -1e30f;
#pragma unroll
    for (int p = 0; p < 24; p++) {
        const float* kr = &ks[c * 196 + p * 8];
        float4 k0 = *reinterpret_cast<const float4*>(kr);
        float4 k1 = *reinterpret_cast<const float4*>(kr + 4);
        float s = q0.x * k0.x + q0.y * k0.y + q0.z * k0.z + q0.w * k0.w +
                  q1.x * k1.x + q1.y * k1.y + q1.z * k1.z + q1.w * k1.w;
        s *= inv_scale;
        sc[p] = s;
        mx = fmaxf(mx, s);
    }
    float ssum = 0.f;
#pragma unroll
    for (int p = 0; p < 24; p++) {
        float e = __expf(sc[p] - mx);
        sc[p] = e;
        ssum += e;
    }
    float inv = 1.f / ssum;
    float o[8] = {0.f, 0.f, 0.f, 0.f, 0.f, 0.f, 0.f, 0.f};
#pragma unroll
    for (int p = 0; p < 24; p++) {
        float a = sc[p] * inv;
        const float* vr = &vs[c * 196 + p * 8];
        float4 v0 = *reinterpret_cast<const float4*>(vr);
        float4 v1 = *reinterpret_cast<const float4*>(vr + 4);
        o[0] = fmaf(a, v0.x, o[0]);
        o[1] = fmaf(a, v0.y, o[1]);
        o[2] = fmaf(a, v0.z, o[2]);
        o[3] = fmaf(a, v0.w, o[3]);
        o[4] = fmaf(a, v1.x, o[4]);
        o[5] = fmaf(a, v1.y, o[5]);
        o[6] = fmaf(a, v1.z, o[6]);
        o[7] = fmaf(a, v1.w, o[7]);
    }
    size_t g = ((size_t)(b * LL + lf) * NN + n) * DDIM + dbase + c * 8;
    *reinterpret_cast<float4*>(&O[g])     = make_float4(o[0], o[1], o[2], o[3]);
    *reinterpret_cast<float4*>(&O[g + 4]) = make_float4(o[4], o[5], o[6], o[7]);
}

// ---------------- final normalize + relu -> d_out ---------------------------
__global__ __launch_bounds__(256) void norm_out_kernel(
    const float* __restrict__ Z, float* __restrict__ out)
{
    size_t i = (size_t)blockIdx.x * 256 + threadIdx.x;
    size_t idx = i * 4;
    int d = (int)(idx & 255);
    float4 z = *reinterpret_cast<const float4*>(&Z[idx]);
    float4 s = *reinterpret_cast<const float4*>(&g_scale[3][d]);
    float4 t = *reinterpret_cast<const float4*>(&g_shift[3][d]);
    float4 r;
    r.x = fmaxf(fmaf(z.x, s.x, t.x), 0.f);
    r.y = fmaxf(fmaf(z.y, s.y, t.y), 0.f);
    r.z = fmaxf(fmaf(z.z, s.z, t.z), 0.f);
    r.w = fmaxf(fmaf(z.w, s.w, t.w), 0.f);
    *reinterpret_cast<float4*>(&out[idx]) = r;
}

// ---------------- launch ------------------------------------------------------
extern "C" void kernel_launch(void* const* d_in, const int* in_sizes, int n_in,
                              void* d_out, int out_size)
{
    const float* x   = (const float*)d_in[0];
    const float* sp  = (const float*)d_in[1];
    const float* sf  = (const float*)d_in[2];
    const float* Wq  = (const float*)d_in[3];
    const float* bq  = (const float*)d_in[4];
    const float* gq  = (const float*)d_in[5];
    const float* beq = (const float*)d_in[6];
    const float* Wk  = (const float*)d_in[7];
    const float* bk  = (const float*)d_in[8];
    const float* gk  = (const float*)d_in[9];
    const float* bek = (const float*)d_in[10];
    const float* Wv  = (const float*)d_in[11];
    const float* bv  = (const float*)d_in[12];
    const float* gv  = (const float*)d_in[13];
    const float* bev = (const float*)d_in[14];
    const float* Wo  = (const float*)d_in[15];
    const float* bo  = (const float*)d_in[16];
    const float* go  = (const float*)d_in[17];
    const float* beo = (const float*)d_in[18];
    float* out = (float*)d_out;

    float *Yq, *Yk, *Yv, *O;
    unsigned short *whi, *wlo;
    cudaGetSymbolAddress((void**)&Yq, g_bufQ);
    cudaGetSymbolAddress((void**)&Yk, g_bufK);
    cudaGetSymbolAddress((void**)&Yv, g_bufV);
    cudaGetSymbolAddress((void**)&O,  g_bufO);
    cudaGetSymbolAddress((void**)&whi, g_Whi);
    cudaGetSymbolAddress((void**)&wlo, g_Wlo);

    cudaFuncSetAttribute(gemm_mma_kernel,
                         cudaFuncAttributeMaxDynamicSharedMemorySize, SM_TOT);

    zero_stats_kernel<<<1, 256>>>();

    conv_w_kernel<<<64, 256>>>(Wq, whi + 0 * 65536, wlo + 0 * 65536);
    conv_w_kernel<<<64, 256>>>(Wk, whi + 1 * 65536, wlo + 1 * 65536);
    conv_w_kernel<<<64, 256>>>(Wv, whi + 2 * 65536, wlo + 2 * 65536);
    conv_w_kernel<<<64, 256>>>(Wo, whi + 3 * 65536, wlo + 3 * 65536);

    const int gblocks = (MROWS / 128) * 2;   // 1950

    gemm_mma_kernel<<<gblocks, 256, SM_TOT>>>(sf, whi + 0 * 65536, wlo + 0 * 65536, bq, Yq, 0);
    gemm_mma_kernel<<<gblocks, 256, SM_TOT>>>(sp, whi + 1 * 65536, wlo + 1 * 65536, bk, Yk, 1);
    gemm_mma_kernel<<<gblocks, 256, SM_TOT>>>(x,  whi + 2 * 65536, wlo + 2 * 65536, bv, Yv, 2);

    finalize_bn_kernel<<<1, 256>>>(gq, beq, 0);
    finalize_bn_kernel<<<1, 256>>>(gk, bek, 1);
    finalize_bn_kernel<<<1, 256>>>(gv, bev, 2);

    attn_kernel<<<BB * NN * 2, 384>>>(Yq, Yk, Yv, O);

    gemm_mma_kernel<<<gblocks, 256, SM_TOT>>>(O, whi + 3 * 65536, wlo + 3 * 65536, bo, Yq, 3);
    finalize_bn_kernel<<<1, 256>>>(go, beo, 3);

    norm_out_kernel<<<(MROWS * DDIM) / (4 * 256), 256>>>(Yq, out);
}

// round 6
// speedup vs baseline: 3.6010x; 1.0835x over previous
#include <cuda_runtime.h>
#include <cstdint>

#define BB 16
#define LL 24
#define NN 325
#define DDIM 256
#define MROWS (BB*LL*NN)   // 124800 = 975 * 128

typedef unsigned long long ULL;

// ---------------- scratch (device globals) ---------------------------------
__device__ float g_bufQ[MROWS * DDIM];
__device__ float g_bufK[MROWS * DDIM];
__device__ float g_bufV[MROWS * DDIM];
__device__ float g_bufO[MROWS * DDIM];

__device__ unsigned short g_Whi[4][DDIM * DDIM];   // [o][k] bf16, transposed
__device__ unsigned short g_Wlo[4][DDIM * DDIM];

__device__ __align__(16) float g_sum[4][DDIM];
__device__ __align__(16) float g_sumsq[4][DDIM];
__device__ __align__(16) float g_scale[4][DDIM];
__device__ __align__(16) float g_shift[4][DDIM];

// ---------------- helpers ----------------------------------------------------
__device__ __forceinline__ uint32_t smem_u32(const void* p) {
    uint32_t a;
    asm("{ .reg .u64 t; cvta.to.shared.u64 t, %1; cvt.u32.u64 %0, t; }"
        : "=r"(a) : "l"(p));
    return a;
}
// packs: upper half = bf16(hiArg), lower half = bf16(loArg)
__device__ __forceinline__ uint32_t cvt2bf(float lo, float hi) {
    uint32_t r;
    asm("cvt.rn.bf16x2.f32 %0, %1, %2;" : "=r"(r) : "f"(hi), "f"(lo));
    return r;
}
__device__ __forceinline__ void ldsm4(uint32_t* r, uint32_t addr) {
    asm volatile("ldmatrix.sync.aligned.m8n8.x4.shared.b16 {%0,%1,%2,%3}, [%4];"
        : "=r"(r[0]), "=r"(r[1]), "=r"(r[2]), "=r"(r[3]) : "r"(addr));
}
__device__ __forceinline__ void mma_bf16(float* c, const uint32_t* a,
                                         uint32_t b0, uint32_t b1) {
    asm volatile(
        "mma.sync.aligned.m16n8k16.row.col.f32.bf16.bf16.f32 "
        "{%0,%1,%2,%3}, {%4,%5,%6,%7}, {%8,%9}, {%0,%1,%2,%3};"
        : "+f"(c[0]), "+f"(c[1]), "+f"(c[2]), "+f"(c[3])
        : "r"(a[0]), "r"(a[1]), "r"(a[2]), "r"(a[3]), "r"(b0), "r"(b1));
}

// ---------------- zero the BN stat accumulators -----------------------------
__global__ void zero_stats_kernel() {
    int t = threadIdx.x;
#pragma unroll
    for (int s = 0; s < 4; s++) { g_sum[s][t] = 0.f; g_sumsq[s][t] = 0.f; }
}

// ---------------- W convert: fp32 [k][o] -> bf16 hi/lo [o][k], 4 sets -------
__global__ void conv_w_kernel(const float* __restrict__ W0,
                              const float* __restrict__ W1,
                              const float* __restrict__ W2,
                              const float* __restrict__ W3) {
    const int set = blockIdx.y;
    const float* W = (set == 0) ? W0 : (set == 1) ? W1 : (set == 2) ? W2 : W3;
    unsigned short* hi = &g_Whi[set][0];
    unsigned short* lo = &g_Wlo[set][0];
    int idx = blockIdx.x * 256 + threadIdx.x;   // grid (64,4)
#pragma unroll
    for (int i = 0; i < 4; i++) {
        int e = idx + i * 16384;                // 65536 elements, [o][k] linear
        int o = e >> 8, k = e & 255;
        float x = W[k * 256 + o];
        unsigned short h;
        asm("cvt.rn.bf16.f32 %0, %1;" : "=h"(h) : "f"(x));
        float fh = __uint_as_float(((uint32_t)h) << 16);
        unsigned short l;
        float res = x - fh;
        asm("cvt.rn.bf16.f32 %0, %1;" : "=h"(l) : "f"(res));
        hi[e] = h;
        lo[e] = l;
    }
}

// ---------------- HMMA bf16x3 GEMM + bias + BN stats -------------------------
// C[m,o] = sum_k X[m,k] W[k,o] + b[o]
// Block: 128(M) x 128(N), 8 warps (4 M-warps x 2 N-warps), warp = 32x64.
// K processed in 4 chunks of 64 bf16; A converted fp32->bf16 hi/lo on the fly.
// Smem tiles 128 rows x 64 bf16 (128B rows) with SW128 xor swizzle.
#define SM_BIAS 0
#define SM_SUM  1024
#define SM_SQ   1536
#define SM_AH   2048
#define SM_AL   (SM_AH + 16384)
#define SM_BH   (SM_AL + 16384)
#define SM_BL   (SM_BH + 16384)
#define SM_TOT  (SM_BL + 16384)    // 67584 bytes

__device__ __forceinline__ void gemm_body(
    const float* __restrict__ X,
    const unsigned short* __restrict__ whi,
    const unsigned short* __restrict__ wlo,
    const float* __restrict__ bias, float* __restrict__ Y, int set,
    char* smem, uint32_t sb)
{
    const int tid  = threadIdx.x;
    const int wid  = tid >> 5, lane = tid & 31;
    const int bm   = blockIdx.x >> 1;
    const int bn   = blockIdx.x & 1;
    const int m0   = bm * 128;
    const int n0g  = bn * 128;
    const int warp_m = wid & 3;      // 0..3 -> M offset *32
    const int warp_n = wid >> 2;     // 0..1 -> N offset *64

    float* bias_s = (float*)(smem + SM_BIAS);
    float* sum_s  = (float*)(smem + SM_SUM);
    float* sq_s   = (float*)(smem + SM_SQ);
    if (tid < 128) {
        bias_s[tid] = bias[n0g + tid];
        sum_s[tid] = 0.f;
        sq_s[tid]  = 0.f;
    }

    float acc[2][8][4];
#pragma unroll
    for (int a = 0; a < 2; a++)
#pragma unroll
        for (int b = 0; b < 8; b++)
#pragma unroll
            for (int c = 0; c < 4; c++) acc[a][b][c] = 0.f;

    // per-lane ldmatrix address components
    const uint32_t swz = (lane & 7) << 4;
    const int a_row = (warp_m * 32) + (lane & 7) + ((lane >> 3) & 1) * 8;
    const int a_kof = (lane >> 4) * 16;
    const int b_row = (warp_n * 64) + (lane & 7) + ((lane >> 4) & 1) * 8;
    const int b_kof = ((lane >> 3) & 1) * 16;
    const uint32_t aH = sb + SM_AH + a_row * 128;
    const uint32_t aL = sb + SM_AL + a_row * 128;
    const uint32_t bH = sb + SM_BH + b_row * 128;
    const uint32_t bL = sb + SM_BL + b_row * 128;

    for (int kc = 0; kc < 4; kc++) {
        const int k0 = kc * 64;
        // ---- A fill: 128 rows x 64 k, fp32 -> bf16 hi/lo ----
#pragma unroll
        for (int i = 0; i < 4; i++) {
            int task = tid + (i << 8);          // 1024 tasks = 128 rows * 8 segs
            int r = task >> 3, seg = task & 7;
            const float4* xp = reinterpret_cast<const float4*>(
                &X[(size_t)(m0 + r) * 256 + k0 + seg * 8]);
            float4 x0 = xp[0], x1 = xp[1];
            uint32_t h01 = cvt2bf(x0.x, x0.y);
            uint32_t h23 = cvt2bf(x0.z, x0.w);
            uint32_t h45 = cvt2bf(x1.x, x1.y);
            uint32_t h67 = cvt2bf(x1.z, x1.w);
            float f0 = __uint_as_float(h01 << 16);
            float f1 = __uint_as_float(h01 & 0xFFFF0000u);
            float f2 = __uint_as_float(h23 << 16);
            float f3 = __uint_as_float(h23 & 0xFFFF0000u);
            float f4 = __uint_as_float(h45 << 16);
            float f5 = __uint_as_float(h45 & 0xFFFF0000u);
            float f6 = __uint_as_float(h67 << 16);
            float f7 = __uint_as_float(h67 & 0xFFFF0000u);
            uint32_t l01 = cvt2bf(x0.x - f0, x0.y - f1);
            uint32_t l23 = cvt2bf(x0.z - f2, x0.w - f3);
            uint32_t l45 = cvt2bf(x1.x - f4, x1.y - f5);
            uint32_t l67 = cvt2bf(x1.z - f6, x1.w - f7);
            int off = r * 128 + ((seg * 16) ^ ((r & 7) << 4));
            *reinterpret_cast<uint4*>(smem + SM_AH + off) =
                make_uint4(h01, h23, h45, h67);
            *reinterpret_cast<uint4*>(smem + SM_AL + off) =
                make_uint4(l01, l23, l45, l67);
        }
        // ---- B fill: 128 n-rows x 64 k, bf16 hi/lo pre-converted ----
#pragma unroll
        for (int i = 0; i < 8; i++) {
            int task = tid + (i << 8);          // 2048
            int half = task >> 10;
            int rem  = task & 1023;
            int r = rem >> 3, seg = rem & 7;
            const unsigned short* src = half ? wlo : whi;
            uint4 v = *reinterpret_cast<const uint4*>(
                &src[(size_t)(n0g + r) * 256 + k0 + seg * 8]);
            int off = r * 128 + ((seg * 16) ^ ((r & 7) << 4));
            *reinterpret_cast<uint4*>(smem + (half ? SM_BL : SM_BH) + off) = v;
        }
        __syncthreads();

        // ---- MMA: 4 k16 steps ----
#pragma unroll
        for (int ks = 0; ks < 4; ks++) {
            const int kb = ks * 32;
            uint32_t ah[2][4], al[2][4];
#pragma unroll
            for (int mi = 0; mi < 2; mi++) {
                uint32_t ko = (uint32_t)(kb + a_kof) ^ swz;
                ldsm4(ah[mi], aH + mi * (16 * 128) + ko);
                ldsm4(al[mi], aL + mi * (16 * 128) + ko);
            }
#pragma unroll
            for (int g = 0; g < 4; g++) {
                uint32_t bh[4], bl[4];
                uint32_t ko = (uint32_t)(kb + b_kof) ^ swz;
                ldsm4(bh, bH + g * (16 * 128) + ko);
                ldsm4(bl, bL + g * (16 * 128) + ko);
#pragma unroll
                for (int mi = 0; mi < 2; mi++) {
                    mma_bf16(acc[mi][2 * g],     ah[mi], bh[0], bh[1]);
                    mma_bf16(acc[mi][2 * g],     al[mi], bh[0], bh[1]);
                    mma_bf16(acc[mi][2 * g],     ah[mi], bl[0], bl[1]);
                    mma_bf16(acc[mi][2 * g + 1], ah[mi], bh[2], bh[3]);
                    mma_bf16(acc[mi][2 * g + 1], al[mi], bh[2], bh[3]);
                    mma_bf16(acc[mi][2 * g + 1], ah[mi], bl[2], bl[3]);
                }
            }
        }
        __syncthreads();
    }

    // ---- epilogue: bias, store, BN stats ----
    const int qrow = lane >> 2;           // 0..7
    const int qcol = (lane & 3) * 2;      // 0,2,4,6
#pragma unroll
    for (int g = 0; g < 4; g++) {
#pragma unroll
        for (int sub = 0; sub < 2; sub++) {
            const int ncol = warp_n * 64 + g * 16 + sub * 8 + qcol;  // 0..127
            const float b0 = bias_s[ncol], b1 = bias_s[ncol + 1];
            float p0 = 0.f, p1 = 0.f, q0 = 0.f, q1 = 0.f;
#pragma unroll
            for (int mi = 0; mi < 2; mi++) {
                const float* a = acc[mi][2 * g + sub];
                float y00 = a[0] + b0, y01 = a[1] + b1;
                float y10 = a[2] + b0, y11 = a[3] + b1;
                const int r = m0 + warp_m * 32 + mi * 16 + qrow;
                *reinterpret_cast<float2*>(&Y[(size_t)r * 256 + n0g + ncol]) =
                    make_float2(y00, y01);
                *reinterpret_cast<float2*>(&Y[(size_t)(r + 8) * 256 + n0g + ncol]) =
                    make_float2(y10, y11);
                p0 += y00 + y10;
                p1 += y01 + y11;
                q0 += y00 * y00 + y10 * y10;
                q1 += y01 * y01 + y11 * y11;
            }
#pragma unroll
            for (int d = 4; d < 32; d <<= 1) {
                p0 += __shfl_xor_sync(0xffffffffu, p0, d);
                p1 += __shfl_xor_sync(0xffffffffu, p1, d);
                q0 += __shfl_xor_sync(0xffffffffu, q0, d);
                q1 += __shfl_xor_sync(0xffffffffu, q1, d);
            }
            if (lane < 4) {
                atomicAdd(&sum_s[ncol], p0);
                atomicAdd(&sum_s[ncol + 1], p1);
                atomicAdd(&sq_s[ncol], q0);
                atomicAdd(&sq_s[ncol + 1], q1);
            }
        }
    }
    __syncthreads();
    if (tid < 128) {
        atomicAdd(&g_sum[set][n0g + tid], sum_s[tid]);
        atomicAdd(&g_sumsq[set][n0g + tid], sq_s[tid]);
    }
}

// merged QKV GEMM: gridDim = (1950, 3)
__global__ __launch_bounds__(256, 2) void gemm_qkv_kernel(
    const float* __restrict__ Xq, const float* __restrict__ Xk,
    const float* __restrict__ Xv,
    const float* __restrict__ bq, const float* __restrict__ bk,
    const float* __restrict__ bv)
{
    extern __shared__ char smem[];
    const uint32_t sb = smem_u32(smem);
    const int set = blockIdx.y;
    const float* X = (set == 0) ? Xq : (set == 1) ? Xk : Xv;
    const float* bias = (set == 0) ? bq : (set == 1) ? bk : bv;
    float* Y = (set == 0) ? g_bufQ : (set == 1) ? g_bufK : g_bufV;
    gemm_body(X, &g_Whi[set][0], &g_Wlo[set][0], bias, Y, set, smem, sb);
}

// single GEMM (output projection), set=3
__global__ __launch_bounds__(256, 2) void gemm_o_kernel(
    const float* __restrict__ bo)
{
    extern __shared__ char smem[];
    const uint32_t sb = smem_u32(smem);
    gemm_body(g_bufO, &g_Whi[3][0], &g_Wlo[3][0], bo, g_bufQ, 3, smem, sb);
}

// ---------------- finalize BN (3 sets in one launch, or single) -------------
__global__ void finalize_bn3_kernel(
    const float* __restrict__ g0, const float* __restrict__ be0,
    const float* __restrict__ g1, const float* __restrict__ be1,
    const float* __restrict__ g2, const float* __restrict__ be2)
{
    int set = blockIdx.x;
    const float* gamma = (set == 0) ? g0 : (set == 1) ? g1 : g2;
    const float* beta  = (set == 0) ? be0 : (set == 1) ? be1 : be2;
    int o = threadIdx.x;
    const float invM = 1.f / (float)MROWS;
    float mu  = g_sum[set][o] * invM;
    float var = g_sumsq[set][o] * invM - mu * mu;
    float sc = gamma[o] * rsqrtf(var + 1e-5f);
    g_scale[set][o] = sc;
    g_shift[set][o] = beta[o] - mu * sc;
}

__global__ void finalize_bn_kernel(const float* __restrict__ gamma,
                                   const float* __restrict__ beta, int set) {
    int o = threadIdx.x;
    const float invM = 1.f / (float)MROWS;
    float mu  = g_sum[set][o] * invM;
    float var = g_sumsq[set][o] * invM - mu * mu;
    float sc = gamma[o] * rsqrtf(var + 1e-5f);
    g_scale[set][o] = sc;
    g_shift[set][o] = beta[o] - mu * sc;
}

// ---------------- attention --------------------------------------------------
__device__ __forceinline__ float4 norm_relu4(float4 y, float4 s, float4 t) {
    float4 r;
    r.x = fmaxf(fmaf(y.x, s.x, t.x), 0.f);
    r.y = fmaxf(fmaf(y.y, s.y, t.y), 0.f);
    r.z = fmaxf(fmaf(y.z, s.z, t.z), 0.f);
    r.w = fmaxf(fmaf(y.w, s.w, t.w), 0.f);
    return r;
}

// One block per (b, n, chunk-half), 384 threads. Task mapping c=task/24,
// lf=task%24 so K/V smem reads BROADCAST across the 24 lanes sharing c.
__global__ __launch_bounds__(384) void attn_kernel(
    const float* __restrict__ Yq, const float* __restrict__ Yk,
    const float* __restrict__ Yv, float* __restrict__ O)
{
    __shared__ float qs[16 * 196];
    __shared__ float ks[16 * 196];
    __shared__ float vs[16 * 196];

    const int blk  = blockIdx.x;
    const int half = blk & 1;
    const int pair = blk >> 1;
    const int b = pair / NN;
    const int n = pair % NN;
    const int dbase = half * 128;

    for (int f = threadIdx.x; f < LL * 32; f += 384) {
        int l   = f >> 5;
        int q4  = f & 31;
        int dd0 = q4 << 2;
        int c   = dd0 >> 3;
        int h0  = dd0 & 7;
        int so  = c * 196 + l * 8 + h0;
        int d0  = dbase + dd0;
        size_t g = ((size_t)(b * LL + l) * NN + n) * DDIM + d0;

        float4 sq = *reinterpret_cast<const float4*>(&g_scale[0][d0]);
        float4 tq = *reinterpret_cast<const float4*>(&g_shift[0][d0]);
        float4 sk = *reinterpret_cast<const float4*>(&g_scale[1][d0]);
        float4 tk = *reinterpret_cast<const float4*>(&g_shift[1][d0]);
        float4 sv = *reinterpret_cast<const float4*>(&g_scale[2][d0]);
        float4 tv = *reinterpret_cast<const float4*>(&g_shift[2][d0]);

        float4 yq = *reinterpret_cast<const float4*>(&Yq[g]);
        float4 yk = *reinterpret_cast<const float4*>(&Yk[g]);
        float4 yv = *reinterpret_cast<const float4*>(&Yv[g]);

        *reinterpret_cast<float4*>(&qs[so]) = norm_relu4(yq, sq, tq);
        *reinterpret_cast<float4*>(&ks[so]) = norm_relu4(yk, sk, tk);
        *reinterpret_cast<float4*>(&vs[so]) = norm_relu4(yv, sv, tv);
    }
    __syncthreads();

    const float inv_scale = 0.17677669529663687f;  // 1/sqrt(32)

    const int task = threadIdx.x;      // 384 tasks = 16 chunks * 24 lf
    const int c  = task / 24;
    const int lf = task - c * 24;
    const float* qr = &qs[c * 196 + lf * 8];
    float4 q0 = *reinterpret_cast<const float4*>(qr);
    float4 q1 = *reinterpret_cast<const float4*>(qr + 4);

    float sc[24];
    float mx = -1e30f;
#pragma unroll
    for (int p = 0; p < 24; p++) {
        const float* kr = &ks[c * 196 + p * 8];   // broadcast within c-group
        float4 k0 = *reinterpret_cast<const float4*>(kr);
        float4 k1 = *reinterpret_cast<const float4*>(kr + 4);
        float s = q0.x * k0.x + q0.y * k0.y + q0.z * k0.z + q0.w * k0.w +
                  q1.x * k1.x + q1.y * k1.y + q1.z * k1.z + q1.w * k1.w;
        s *= inv_scale;
        sc[p] = s;
        mx = fmaxf(mx, s);
    }
    float ssum = 0.f;
#pragma unroll
    for (int p = 0; p < 24; p++) {
        float e = __expf(sc[p] - mx);
        sc[p] = e;
        ssum += e;
    }
    float inv = 1.f / ssum;
    float o[8] = {0.f, 0.f, 0.f, 0.f, 0.f, 0.f, 0.f, 0.f};
#pragma unroll
    for (int p = 0; p < 24; p++) {
        float a = sc[p] * inv;
        const float* vr = &vs[c * 196 + p * 8];   // broadcast within c-group
        float4 v0 = *reinterpret_cast<const float4*>(vr);
        float4 v1 = *reinterpret_cast<const float4*>(vr + 4);
        o[0] = fmaf(a, v0.x, o[0]);
        o[1] = fmaf(a, v0.y, o[1]);
        o[2] = fmaf(a, v0.z, o[2]);
        o[3] = fmaf(a, v0.w, o[3]);
        o[4] = fmaf(a, v1.x, o[4]);
        o[5] = fmaf(a, v1.y, o[5]);
        o[6] = fmaf(a, v1.z, o[6]);
        o[7] = fmaf(a, v1.w, o[7]);
    }
    size_t g = ((size_t)(b * LL + lf) * NN + n) * DDIM + dbase + c * 8;
    *reinterpret_cast<float4*>(&O[g])     = make_float4(o[0], o[1], o[2], o[3]);
    *reinterpret_cast<float4*>(&O[g + 4]) = make_float4(o[4], o[5], o[6], o[7]);
}

// ---------------- final normalize + relu -> d_out ---------------------------
__global__ __launch_bounds__(256) void norm_out_kernel(
    const float* __restrict__ Z, float* __restrict__ out)
{
    size_t i = (size_t)blockIdx.x * 256 + threadIdx.x;
    size_t idx = i * 4;
    int d = (int)(idx & 255);
    float4 z = *reinterpret_cast<const float4*>(&Z[idx]);
    float4 s = *reinterpret_cast<const float4*>(&g_scale[3][d]);
    float4 t = *reinterpret_cast<const float4*>(&g_shift[3][d]);
    float4 r;
    r.x = fmaxf(fmaf(z.x, s.x, t.x), 0.f);
    r.y = fmaxf(fmaf(z.y, s.y, t.y), 0.f);
    r.z = fmaxf(fmaf(z.z, s.z, t.z), 0.f);
    r.w = fmaxf(fmaf(z.w, s.w, t.w), 0.f);
    *reinterpret_cast<float4*>(&out[idx]) = r;
}

// ---------------- launch ------------------------------------------------------
extern "C" void kernel_launch(void* const* d_in, const int* in_sizes, int n_in,
                              void* d_out, int out_size)
{
    const float* x   = (const float*)d_in[0];
    const float* sp  = (const float*)d_in[1];
    const float* sf  = (const float*)d_in[2];
    const float* Wq  = (const float*)d_in[3];
    const float* bq  = (const float*)d_in[4];
    const float* gq  = (const float*)d_in[5];
    const float* beq = (const float*)d_in[6];
    const float* Wk  = (const float*)d_in[7];
    const float* bk  = (const float*)d_in[8];
    const float* gk  = (const float*)d_in[9];
    const float* bek = (const float*)d_in[10];
    const float* Wv  = (const float*)d_in[11];
    const float* bv  = (const float*)d_in[12];
    const float* gv  = (const float*)d_in[13];
    const float* bev = (const float*)d_in[14];
    const float* Wo  = (const float*)d_in[15];
    const float* bo  = (const float*)d_in[16];
    const float* go  = (const float*)d_in[17];
    const float* beo = (const float*)d_in[18];
    float* out = (float*)d_out;

    float *Yq, *Yk, *Yv, *O;
    cudaGetSymbolAddress((void**)&Yq, g_bufQ);
    cudaGetSymbolAddress((void**)&Yk, g_bufK);
    cudaGetSymbolAddress((void**)&Yv, g_bufV);
    cudaGetSymbolAddress((void**)&O,  g_bufO);

    cudaFuncSetAttribute(gemm_qkv_kernel,
                         cudaFuncAttributeMaxDynamicSharedMemorySize, SM_TOT);
    cudaFuncSetAttribute(gemm_o_kernel,
                         cudaFuncAttributeMaxDynamicSharedMemorySize, SM_TOT);

    zero_stats_kernel<<<1, 256>>>();
    conv_w_kernel<<<dim3(64, 4), 256>>>(Wq, Wk, Wv, Wo);

    const int gblocks = (MROWS / 128) * 2;   // 1950

    gemm_qkv_kernel<<<dim3(gblocks, 3), 256, SM_TOT>>>(sf, sp, x, bq, bk, bv);

    finalize_bn3_kernel<<<3, 256>>>(gq, beq, gk, bek, gv, bev);

    attn_kernel<<<BB * NN * 2, 384>>>(Yq, Yk, Yv, O);

    gemm_o_kernel<<<gblocks, 256, SM_TOT>>>(bo);
    finalize_bn_kernel<<<1, 256>>>(go, beo, 3);

    norm_out_kernel<<<(MROWS * DDIM) / (4 * 256), 256>>>(Yq, out);
}